// round 6
// baseline (speedup 1.0000x reference)
#include <cuda_runtime.h>
#include <math.h>

#define HALFC 4194304u   // chain (n0+512) flat-index offset = 512*8192

struct Params {
    float beta[18];
    unsigned fk0[16];
    unsigned fk1[16];
};

// -------- device scratch (allocation-free) --------
__device__ float g_M[4096];                   // W_dec W_dec^T
__device__ float g_mu[8192];                  // [b][d]
__device__ float g_xWt[8192];                 // [b][d] x W_dec^T
__device__ float g_muT[8192];                 // [d][b]
__device__ unsigned long long g_xP[4096];     // [e2][b] packed (x[2e2], x[2e2+1])
__device__ float g_cb[128];                   // 0.5||mu||^2 - 32 log 2pi
__device__ float g_P[16 * 4096];              // q propagator per step
__device__ float g_Q[16 * 4096];              // noise propagator per step
__device__ unsigned long long g_dTP[16 * 4096];  // [k][e2][b] packed drift
__device__ float g_slw[131072];               // [b][n]

// ---------------------------------------------------------------------------
// threefry2x32 — exact JAX schedule
// ---------------------------------------------------------------------------
__host__ __device__ __forceinline__ void tf2x32(unsigned k0, unsigned k1,
                                                unsigned x0, unsigned x1,
                                                unsigned* o0, unsigned* o1) {
    unsigned k2 = k0 ^ k1 ^ 0x1BD11BDAu;
    x0 += k0; x1 += k1;
#define TFR(r) { x0 += x1; x1 = (x1 << (r)) | (x1 >> (32 - (r))); x1 ^= x0; }
    TFR(13) TFR(15) TFR(26) TFR(6)
    x0 += k1; x1 += k2 + 1u;
    TFR(17) TFR(29) TFR(16) TFR(24)
    x0 += k2; x1 += k0 + 2u;
    TFR(13) TFR(15) TFR(26) TFR(6)
    x0 += k0; x1 += k1 + 3u;
    TFR(17) TFR(29) TFR(16) TFR(24)
    x0 += k1; x1 += k2 + 4u;
    TFR(13) TFR(15) TFR(26) TFR(6)
    x0 += k2; x1 += k0 + 5u;
#undef TFR
    *o0 = x0; *o1 = x1;
}

// partitionable-mode element draw: bits = out0 ^ out1 of cipher(key, (0, idx))
__device__ __forceinline__ float draw_normal(unsigned fk0, unsigned fk1, unsigned idx) {
    unsigned r0, r1;
    tf2x32(fk0, fk1, 0u, idx, &r0, &r1);
    unsigned bits = r0 ^ r1;
    float f = __uint_as_float((bits >> 9) | 0x3f800000u) - 1.0f;  // [0,1)
    const float lo = -0.99999994f;                 // nextafterf(-1,0)
    float v = fmaf(f, 2.0f, lo);                   // (hi-lo) rounds to exactly 2.0f
    v = fmaxf(lo, v);
    return 1.41421356f * erfinvf(v);
}

// -------- packed f32x2 helpers (Blackwell) --------
__device__ __forceinline__ unsigned long long pack2(float a, float b) {
    unsigned long long r;
    asm("mov.b64 %0, {%1, %2};" : "=l"(r) : "f"(a), "f"(b));
    return r;
}
__device__ __forceinline__ void unpack2(unsigned long long v, float& a, float& b) {
    asm("mov.b64 {%0, %1}, %2;" : "=f"(a), "=f"(b) : "l"(v));
}
#define FMA2(c, a, bb) asm("fma.rn.f32x2 %0, %1, %2, %0;" : "+l"(c) : "l"(a), "l"(bb))

// ---------------------------------------------------------------------------
// setup 1: M, mu/muT, xWt, packed x
// ---------------------------------------------------------------------------
__global__ void k_setup1(const float* __restrict__ x,
                         const float* __restrict__ We,
                         const float* __restrict__ Wd) {
    int idx = blockIdx.x * 256 + threadIdx.x;
    if (idx < 4096) {
        int i = idx >> 6, j = idx & 63;
        float s = 0.f;
        for (int e = 0; e < 64; e++) s = fmaf(Wd[i * 64 + e], Wd[j * 64 + e], s);
        g_M[idx] = s;
    } else if (idx < 12288) {
        int o = idx - 4096; int b = o >> 6, d = o & 63;
        float sm = 0.f, sw = 0.f;
        for (int e = 0; e < 64; e++) {
            float xe = x[b * 64 + e];
            sm = fmaf(xe, We[e * 64 + d], sm);
            sw = fmaf(xe, Wd[d * 64 + e], sw);
        }
        g_mu[o] = sm; g_muT[d * 128 + b] = sm; g_xWt[o] = sw;
    } else if (idx < 16384) {
        int o = idx - 12288; int b = o >> 5, e2 = o & 31;
        g_xP[e2 * 128 + b] = pack2(x[b * 64 + 2 * e2], x[b * 64 + 2 * e2 + 1]);
    }
}

__global__ void k_setup2() {
    int b = threadIdx.x;
    float s = 0.f;
    for (int d = 0; d < 64; d++) { float m = g_mu[b * 64 + d]; s = fmaf(m, m, s); }
    g_cb[b] = 0.5f * s - 58.81206612509905f;  // -32*log(2*pi)
}

// ---------------------------------------------------------------------------
// setup 3 (block k): C = h^2(bk M + I); P = I-4.5C+3C^2-0.5C^3;
// Q = h(3I-4C+C^2); d = h^2(4.5I-3C+0.5C^2) v,  v = bk xWt + (1-bk) mu
// ---------------------------------------------------------------------------
__global__ void k_setup3(Params prm) {
    __shared__ float sC[4096], sC2[4096];
    const int k = blockIdx.x;
    const float bk = prm.beta[k + 1];
    const int t = threadIdx.x;
    const float h = 0.05f, h2 = 0.0025f;
    for (int o = t; o < 4096; o += 256) {
        int i = o >> 6, j = o & 63;
        sC[o] = h2 * (bk * g_M[o] + ((i == j) ? 1.f : 0.f));
    }
    __syncthreads();
    for (int o = t; o < 4096; o += 256) {
        int i = o >> 6, j = o & 63;
        float s = 0.f;
        for (int l = 0; l < 64; l++) s = fmaf(sC[i * 64 + l], sC[l * 64 + j], s);
        sC2[o] = s;
    }
    __syncthreads();
    for (int o = t; o < 4096; o += 256) {
        int i = o >> 6, j = o & 63;
        float c3 = 0.f;
        for (int l = 0; l < 64; l++) c3 = fmaf(sC2[i * 64 + l], sC[l * 64 + j], c3);
        float del = (i == j) ? 1.f : 0.f;
        g_P[k * 4096 + o] = del - 4.5f * sC[o] + 3.f * sC2[o] - 0.5f * c3;
        g_Q[k * 4096 + o] = h * (3.f * del - 4.f * sC[o] + sC2[o]);
    }
    for (int o = t; o < 4096; o += 256) {
        int b = o >> 5, i2 = o & 31;
        float out[2];
#pragma unroll
        for (int hh = 0; hh < 2; hh++) {
            int i = 2 * i2 + hh;
            float cv = 0.f, c2v = 0.f;
            for (int l = 0; l < 64; l++) {
                float v = bk * g_xWt[b * 64 + l] + (1.f - bk) * g_mu[b * 64 + l];
                cv  = fmaf(sC[i * 64 + l],  v, cv);
                c2v = fmaf(sC2[i * 64 + l], v, c2v);
            }
            float vi = bk * g_xWt[b * 64 + i] + (1.f - bk) * g_mu[b * 64 + i];
            out[hh] = h2 * (4.5f * vi - 3.f * cv + 0.5f * c2v);
        }
        g_dTP[k * 4096 + i2 * 128 + b] = pack2(out[0], out[1]);
    }
}

// ---------------------------------------------------------------------------
// weight: w = cb - 0.5||x - qW||^2 - q.mu   (two chains, packed e-pairs)
// ---------------------------------------------------------------------------
__device__ __forceinline__ void weight2(
    const unsigned long long* __restrict__ sq1,
    const unsigned long long* __restrict__ sq2,
    const float* __restrict__ sW, int t, int b, float cb,
    unsigned long long* __restrict__ a1, unsigned long long* __restrict__ a2,
    float& w1, float& w2)
{
#pragma unroll
    for (int p = 0; p < 32; p++) { a1[p] = 0ull; a2[p] = 0ull; }
    float dot1 = 0.f, dot2 = 0.f;
#pragma unroll
    for (int p = 0; p < 32; p++) {
        float qa1, qb1, qa2, qb2;
        unpack2(sq1[p * 256 + t], qa1, qb1);
        unpack2(sq2[p * 256 + t], qa2, qb2);
        float mua = g_muT[(2 * p) * 128 + b];
        float mub = g_muT[(2 * p + 1) * 128 + b];
        dot1 = fmaf(qa1, mua, fmaf(qb1, mub, dot1));
        dot2 = fmaf(qa2, mua, fmaf(qb2, mub, dot2));
        unsigned long long pa1 = pack2(qa1, qa1), pb1 = pack2(qb1, qb1);
        unsigned long long pa2 = pack2(qa2, qa2), pb2 = pack2(qb2, qb2);
        const ulonglong2* rowA = (const ulonglong2*)(sW + (2 * p) * 64);
        const ulonglong2* rowB = (const ulonglong2*)(sW + (2 * p + 1) * 64);
#pragma unroll
        for (int j = 0; j < 16; j++) {
            ulonglong2 wa = rowA[j];
            ulonglong2 wb = rowB[j];
            FMA2(a1[2 * j],     pa1, wa.x); FMA2(a1[2 * j + 1], pa1, wa.y);
            FMA2(a1[2 * j],     pb1, wb.x); FMA2(a1[2 * j + 1], pb1, wb.y);
            FMA2(a2[2 * j],     pa2, wa.x); FMA2(a2[2 * j + 1], pa2, wa.y);
            FMA2(a2[2 * j],     pb2, wb.x); FMA2(a2[2 * j + 1], pb2, wb.y);
        }
    }
    unsigned long long s1 = 0ull, s2 = 0ull;
    const unsigned long long neg1 = 0xBF800000BF800000ull;  // (-1.f,-1.f)
#pragma unroll
    for (int p = 0; p < 32; p++) {
        unsigned long long xp = g_xP[p * 128 + b];
        unsigned long long t1 = xp; FMA2(t1, a1[p], neg1); FMA2(s1, t1, t1);
        unsigned long long t2 = xp; FMA2(t2, a2[p], neg1); FMA2(s2, t2, t2);
    }
    float s1a, s1b, s2a, s2b;
    unpack2(s1, s1a, s1b); unpack2(s2, s2a, s2b);
    w1 = cb - 0.5f * (s1a + s1b) - dot1;
    w2 = cb - 0.5f * (s2a + s2b) - dot2;
}

// ---------------------------------------------------------------------------
// main: thread = (b, n0) pair handling chains n0 and n0+512
// smem: sq1,sq2 (u64 cols, 64KB each) + sP + sQ + sW = 180224 B
// ---------------------------------------------------------------------------
__global__ void __launch_bounds__(256, 1) k_main(const float* __restrict__ qn,
                                                 const float* __restrict__ Wd,
                                                 Params prm)
{
    extern __shared__ float smem[];
    unsigned long long* sq1 = (unsigned long long*)smem;             // 32*256 u64
    unsigned long long* sq2 = (unsigned long long*)(smem + 16384);   // 32*256 u64
    float* sP  = smem + 32768;
    float* sQm = smem + 36864;
    float* sW  = smem + 40960;
    const int t  = threadIdx.x;
    const int b  = t & 127;
    const int n0 = blockIdx.x * 2 + (t >> 7);
    const unsigned base = (unsigned)n0 * 8192u + (unsigned)b * 64u;

    for (int i = t; i < 1024; i += 256) ((float4*)sW)[i] = ((const float4*)Wd)[i];

    // q0 = mu + q_noise (both chains)
    const float2* qn1 = (const float2*)(qn + base);
    const float2* qn2 = (const float2*)(qn + base + HALFC);
#pragma unroll
    for (int p = 0; p < 32; p++) {
        float m0 = g_muT[(2 * p) * 128 + b];
        float m1 = g_muT[(2 * p + 1) * 128 + b];
        float2 u1 = qn1[p];
        float2 u2 = qn2[p];
        sq1[p * 256 + t] = pack2(m0 + u1.x, m1 + u1.y);
        sq2[p * 256 + t] = pack2(m0 + u2.x, m1 + u2.y);
    }
    __syncthreads();

    const float cb = g_cb[b];
    unsigned long long a1[32], a2[32];
    float slw1, slw2;
    {
        float w1, w2;
        weight2(sq1, sq2, sW, t, b, cb, a1, a2, w1, w2);
        float db = prm.beta[1] - prm.beta[0];
        slw1 = db * w1; slw2 = db * w2;
    }

    for (int k = 0; k < 16; k++) {
        __syncthreads();
        for (int i = t; i < 1024; i += 256) {
            ((float4*)sP)[i]  = ((const float4*)(g_P + k * 4096))[i];
            ((float4*)sQm)[i] = ((const float4*)(g_Q + k * 4096))[i];
        }
        __syncthreads();

        // acc = drift (same for both chains: same b, same k)
#pragma unroll
        for (int p = 0; p < 32; p++) {
            unsigned long long dv = g_dTP[k * 4096 + p * 128 + b];
            a1[p] = dv; a2[p] = dv;
        }
        // acc += q P
#pragma unroll
        for (int p = 0; p < 32; p++) {
            float qa1, qb1, qa2, qb2;
            unpack2(sq1[p * 256 + t], qa1, qb1);
            unpack2(sq2[p * 256 + t], qa2, qb2);
            unsigned long long pa1 = pack2(qa1, qa1), pb1 = pack2(qb1, qb1);
            unsigned long long pa2 = pack2(qa2, qa2), pb2 = pack2(qb2, qb2);
            const ulonglong2* rowA = (const ulonglong2*)(sP + (2 * p) * 64);
            const ulonglong2* rowB = (const ulonglong2*)(sP + (2 * p + 1) * 64);
#pragma unroll
            for (int j = 0; j < 16; j++) {
                ulonglong2 wa = rowA[j];
                ulonglong2 wb = rowB[j];
                FMA2(a1[2 * j],     pa1, wa.x); FMA2(a1[2 * j + 1], pa1, wa.y);
                FMA2(a1[2 * j],     pb1, wb.x); FMA2(a1[2 * j + 1], pb1, wb.y);
                FMA2(a2[2 * j],     pa2, wa.x); FMA2(a2[2 * j + 1], pa2, wa.y);
                FMA2(a2[2 * j],     pb2, wb.x); FMA2(a2[2 * j + 1], pb2, wb.y);
            }
        }
        // acc += eps Q  (partitionable: per-element cipher, xor-fold)
        const unsigned fk0 = prm.fk0[k], fk1 = prm.fk1[k];
#pragma unroll 2
        for (int d = 0; d < 64; d++) {
            unsigned idx = base + (unsigned)d;
            float e1 = draw_normal(fk0, fk1, idx);
            float e2 = draw_normal(fk0, fk1, idx + HALFC);
            unsigned long long pe1 = pack2(e1, e1);
            unsigned long long pe2 = pack2(e2, e2);
            const ulonglong2* row = (const ulonglong2*)(sQm + d * 64);
#pragma unroll
            for (int j = 0; j < 16; j++) {
                ulonglong2 w = row[j];
                FMA2(a1[2 * j],     pe1, w.x); FMA2(a1[2 * j + 1], pe1, w.y);
                FMA2(a2[2 * j],     pe2, w.x); FMA2(a2[2 * j + 1], pe2, w.y);
            }
        }
        // q <- acc (own column only; no barrier needed)
#pragma unroll
        for (int p = 0; p < 32; p++) {
            sq1[p * 256 + t] = a1[p];
            sq2[p * 256 + t] = a2[p];
        }
        {
            float w1, w2;
            weight2(sq1, sq2, sW, t, b, cb, a1, a2, w1, w2);
            float db = prm.beta[k + 2] - prm.beta[k + 1];
            slw1 = fmaf(db, w1, slw1);
            slw2 = fmaf(db, w2, slw2);
        }
    }
    g_slw[b * 1024 + n0]       = slw1;
    g_slw[b * 1024 + n0 + 512] = slw2;
}

// ---------------------------------------------------------------------------
// logsumexp over n, minus log(1024)
// ---------------------------------------------------------------------------
__global__ void k_reduce(float* __restrict__ out) {
    const int b = blockIdx.x;
    const int t = threadIdx.x;          // 128
    __shared__ float red[128];
    float m = -3.4e38f;
    for (int i = t; i < 1024; i += 128) m = fmaxf(m, g_slw[b * 1024 + i]);
    red[t] = m; __syncthreads();
    for (int s = 64; s > 0; s >>= 1) {
        if (t < s) red[t] = fmaxf(red[t], red[t + s]);
        __syncthreads();
    }
    float mx = red[0]; __syncthreads();
    float acc = 0.f;
    for (int i = t; i < 1024; i += 128) acc += expf(g_slw[b * 1024 + i] - mx);
    red[t] = acc; __syncthreads();
    for (int s = 64; s > 0; s >>= 1) {
        if (t < s) red[t] += red[t + s];
        __syncthreads();
    }
    if (t == 0) out[b] = mx + logf(red[0]) - 6.9314718055994531f;  // log(1024)
}

// ---------------------------------------------------------------------------
extern "C" void kernel_launch(void* const* d_in, const int* in_sizes, int n_in,
                              void* d_out, int out_size) {
    const float* x    = (const float*)d_in[0];
    const float* Wenc = (const float*)d_in[1];
    const float* Wdec = (const float*)d_in[2];
    const float* qn   = (const float*)d_in[3];
    // d_in[4] = p_noise — provably unused (momentum fully resampled each step)
    float* out = (float*)d_out;

    Params prm;
    double bb[18];
    for (int i = 0; i < 18; i++) {
        double z = 4.0 * (2.0 * ((double)i / 17.0) - 1.0);
        bb[i] = 1.0 / (1.0 + exp(-z));
    }
    for (int i = 0; i < 18; i++)
        prm.beta[i] = (float)((bb[i] - bb[0]) / (bb[17] - bb[0]));
    for (int k = 1; k <= 16; k++) {
        unsigned o0, o1;
        tf2x32(0u, 42u, 0u, (unsigned)k, &o0, &o1);   // fold_in(key(42), k)
        prm.fk0[k - 1] = o0; prm.fk1[k - 1] = o1;
    }

    cudaFuncSetAttribute(k_main, cudaFuncAttributeMaxDynamicSharedMemorySize, 45056 * 4);

    k_setup1<<<64, 256>>>(x, Wenc, Wdec);
    k_setup2<<<1, 128>>>();
    k_setup3<<<16, 256>>>(prm);
    k_main<<<256, 256, 45056 * 4>>>(qn, Wdec, prm);
    k_reduce<<<128, 128>>>(out);
}

// round 7
// speedup vs baseline: 2.5936x; 2.5936x over previous
#include <cuda_runtime.h>
#include <math.h>

struct Params {
    float beta[18];
    unsigned fk0[16];
    unsigned fk1[16];
};

// -------- device scratch (allocation-free, module statics) --------
__device__ float g_M[4096];          // W_dec W_dec^T
__device__ float g_mu[8192];         // [b][d]
__device__ float g_xWt[8192];        // [b][d] x W_dec^T
__device__ float g_V[4096];          // eigenvectors [d][i]
__device__ float g_lam[64];          // eigenvalues
__device__ float g_mtT[8192];        // [i][b]  mu~  (mu V)
__device__ float g_xtT[8192];        // [i][b]  xWt~ (xWt V)
__device__ float g_uT[8192];         // [i][b]  u~ = xWt~ - mu~
__device__ float g_cw[128];          // const_b
__device__ float g_pc[1024];         // [k][i] p coefficient
__device__ float g_qd[1024];         // [k][i] noise coefficient
__device__ float g_dT[16 * 8192];    // [k][i][b] drift
__device__ float g_epst[134217728];  // [k][i][chain] qd*eps~ + d~  (512MB)
__device__ float g_slw[131072];      // [b][n]

// ---------------------------------------------------------------------------
// threefry2x32 — exact JAX schedule
// ---------------------------------------------------------------------------
__host__ __device__ __forceinline__ void tf2x32(unsigned k0, unsigned k1,
                                                unsigned x0, unsigned x1,
                                                unsigned* o0, unsigned* o1) {
    unsigned k2 = k0 ^ k1 ^ 0x1BD11BDAu;
    x0 += k0; x1 += k1;
#define TFR(r) { x0 += x1; x1 = (x1 << (r)) | (x1 >> (32 - (r))); x1 ^= x0; }
    TFR(13) TFR(15) TFR(26) TFR(6)
    x0 += k1; x1 += k2 + 1u;
    TFR(17) TFR(29) TFR(16) TFR(24)
    x0 += k2; x1 += k0 + 2u;
    TFR(13) TFR(15) TFR(26) TFR(6)
    x0 += k0; x1 += k1 + 3u;
    TFR(17) TFR(29) TFR(16) TFR(24)
    x0 += k1; x1 += k2 + 4u;
    TFR(13) TFR(15) TFR(26) TFR(6)
    x0 += k2; x1 += k0 + 5u;
#undef TFR
    *o0 = x0; *o1 = x1;
}

// partitionable-mode draw: bits = out0 ^ out1 of cipher(key, (0, idx))
__device__ __forceinline__ float draw_normal(unsigned fk0, unsigned fk1, unsigned idx) {
    unsigned r0, r1;
    tf2x32(fk0, fk1, 0u, idx, &r0, &r1);
    unsigned bits = r0 ^ r1;
    float f = __uint_as_float((bits >> 9) | 0x3f800000u) - 1.0f;  // [0,1)
    const float lo = -0.99999994f;                  // nextafterf(-1,0)
    float v = fmaf(f, 2.0f, lo);                    // (hi-lo) == 2.0f in fp32
    v = fmaxf(lo, v);
    return 1.41421356f * erfinvf(v);
}

// -------- packed f32x2 helpers --------
__device__ __forceinline__ unsigned long long pack2(float a, float b) {
    unsigned long long r;
    asm("mov.b64 %0, {%1, %2};" : "=l"(r) : "f"(a), "f"(b));
    return r;
}
__device__ __forceinline__ void unpack2(unsigned long long v, float& a, float& b) {
    asm("mov.b64 {%0, %1}, %2;" : "=f"(a), "=f"(b) : "l"(v));
}
#define FMA2(c, a, bb) asm("fma.rn.f32x2 %0, %1, %2, %0;" : "+l"(c) : "l"(a), "l"(bb))

// ---------------------------------------------------------------------------
// setup: M, mu, xWt
// ---------------------------------------------------------------------------
__global__ void k_setup1(const float* __restrict__ x,
                         const float* __restrict__ We,
                         const float* __restrict__ Wd) {
    int idx = blockIdx.x * 256 + threadIdx.x;
    if (idx < 4096) {
        int i = idx >> 6, j = idx & 63;
        float s = 0.f;
        for (int e = 0; e < 64; e++) s = fmaf(Wd[i * 64 + e], Wd[j * 64 + e], s);
        g_M[idx] = s;
    } else if (idx < 12288) {
        int o = idx - 4096; int b = o >> 6, d = o & 63;
        float sm = 0.f, sw = 0.f;
        for (int e = 0; e < 64; e++) {
            float xe = x[b * 64 + e];
            sm = fmaf(xe, We[e * 64 + d], sm);
            sw = fmaf(xe, Wd[d * 64 + e], sw);
        }
        g_mu[o] = sm; g_xWt[o] = sw;
    }
}

// const_b = 0.5||mu||^2 - 0.5||x||^2 - 32 log 2pi
__global__ void k_cw(const float* __restrict__ x) {
    int b = threadIdx.x;
    float s = 0.f, sx = 0.f;
    for (int d = 0; d < 64; d++) {
        float m = g_mu[b * 64 + d]; s = fmaf(m, m, s);
        float xe = x[b * 64 + d];   sx = fmaf(xe, xe, sx);
    }
    g_cw[b] = 0.5f * s - 0.5f * sx - 58.81206612509905f;
}

// ---------------------------------------------------------------------------
// parallel two-sided Jacobi eigensolver, 64x64, one block of 1024 threads.
// Round-robin pairing via closed-form (player 63 fixed):
//   round r: pair m=0: (63, r); m=1..31: ((r+m)%63, (r-m+63)%63)
// ---------------------------------------------------------------------------
__global__ void __launch_bounds__(1024) k_jacobi() {
    __shared__ float A[64][65];
    __shared__ float Vv[64][65];
    __shared__ float cs[32], sn[32];
    __shared__ int pp[32], qq[32];
    const int t = threadIdx.x;
    for (int o = t; o < 4096; o += 1024) {
        int i = o >> 6, j = o & 63;
        A[i][j] = g_M[o];
        Vv[i][j] = (i == j) ? 1.f : 0.f;
    }
    __syncthreads();
    for (int sweep = 0; sweep < 9; sweep++) {
        for (int r = 0; r < 63; r++) {
            if (t < 32) {
                int p, q;
                if (t == 0) { p = 63; q = r; }
                else { p = (r + t) % 63; q = (r - t + 63) % 63; }
                if (p > q) { int tmp = p; p = q; q = tmp; }
                pp[t] = p; qq[t] = q;
                float apq = A[p][q], app = A[p][p], aqq = A[q][q];
                float c = 1.f, s = 0.f;
                if (fabsf(apq) > 1e-30f) {
                    float tau = (aqq - app) / (2.f * apq);
                    float tt = ((tau >= 0.f) ? 1.f : -1.f) /
                               (fabsf(tau) + sqrtf(1.f + tau * tau));
                    c = rsqrtf(1.f + tt * tt);
                    s = tt * c;
                }
                cs[t] = c; sn[t] = s;
            }
            __syncthreads();
            // row phase
            for (int u = t; u < 2048; u += 1024) {
                int m = u >> 6, j = u & 63;
                int p = pp[m], q = qq[m];
                float c = cs[m], s = sn[m];
                float ap = A[p][j], aq = A[q][j];
                A[p][j] = c * ap - s * aq;
                A[q][j] = s * ap + c * aq;
            }
            __syncthreads();
            // col phase + V update
            for (int u = t; u < 2048; u += 1024) {
                int m = u >> 6, i = u & 63;
                int p = pp[m], q = qq[m];
                float c = cs[m], s = sn[m];
                float ap = A[i][p], aq = A[i][q];
                A[i][p] = c * ap - s * aq;
                A[i][q] = s * ap + c * aq;
                float vp = Vv[i][p], vq = Vv[i][q];
                Vv[i][p] = c * vp - s * vq;
                Vv[i][q] = s * vp + c * vq;
            }
            __syncthreads();
        }
    }
    for (int o = t; o < 4096; o += 1024) g_V[o] = Vv[o >> 6][o & 63];
    if (t < 64) g_lam[t] = A[t][t];
}

// ---------------------------------------------------------------------------
// transform mu, xWt into eigenbasis: [i][b] tables
// ---------------------------------------------------------------------------
__global__ void k_trans() {
    int o = blockIdx.x * 256 + threadIdx.x;   // 8192
    int b = o >> 6, i = o & 63;
    float sm = 0.f, sx = 0.f;
    for (int d = 0; d < 64; d++) {
        float v = g_V[d * 64 + i];
        sm = fmaf(g_mu[b * 64 + d], v, sm);
        sx = fmaf(g_xWt[b * 64 + d], v, sx);
    }
    g_mtT[i * 128 + b] = sm;
    g_xtT[i * 128 + b] = sx;
    g_uT[i * 128 + b] = sx - sm;
}

// ---------------------------------------------------------------------------
// per-step scalar coefficients + drift (all diagonal in eigenbasis)
// c = h^2(bk*lam+1); p = 1-4.5c+3c^2-0.5c^3; qd = h(3-4c+c^2);
// d~ = h^2(4.5-3c+0.5c^2) * (bk*xWt~ + (1-bk)*mu~)
// ---------------------------------------------------------------------------
__global__ void k_coef(Params prm) {
    const int k = blockIdx.x;
    const float bk = prm.beta[k + 1];
    const float h = 0.05f, h2 = 0.0025f;
    for (int o = threadIdx.x; o < 8192; o += 256) {
        int i = o >> 7, b = o & 127;
        float lam = g_lam[i];
        float c = h2 * (bk * lam + 1.f);
        float sd = h2 * (4.5f - 3.f * c + 0.5f * c * c);
        float vt = bk * g_xtT[i * 128 + b] + (1.f - bk) * g_mtT[i * 128 + b];
        g_dT[(k * 64 + i) * 128 + b] = sd * vt;
        if (b == 0) {
            g_pc[k * 64 + i] = 1.f - 4.5f * c + 3.f * c * c - 0.5f * c * c * c;
            g_qd[k * 64 + i] = h * (3.f - 4.f * c + c * c);
        }
    }
}

// ---------------------------------------------------------------------------
// k_eps: stateless over (chain, step). Draw 64 eps, eps~ = eps V (with qd
// folded into V), add drift, store to g_epst[k][i][chain].
// ---------------------------------------------------------------------------
__global__ void __launch_bounds__(256) k_eps(Params prm) {
    __shared__ float sVq[4096];               // [d][i] = V[d][i] * qd[k][i]
    const int k  = blockIdx.x >> 9;
    const int cb = blockIdx.x & 511;
    const int t  = threadIdx.x;
    const unsigned chain = (unsigned)cb * 256u + (unsigned)t;
    for (int o = t; o < 4096; o += 256)
        sVq[o] = g_V[o] * g_qd[k * 64 + (o & 63)];
    __syncthreads();

    const unsigned fk0 = prm.fk0[k], fk1 = prm.fk1[k];
    const unsigned base = chain * 64u;
    unsigned long long acc[32];
#pragma unroll
    for (int j = 0; j < 32; j++) acc[j] = 0ull;

#pragma unroll 2
    for (int d = 0; d < 64; d++) {
        float e = draw_normal(fk0, fk1, base + (unsigned)d);
        unsigned long long pe = pack2(e, e);
        const ulonglong2* row = (const ulonglong2*)(sVq + d * 64);
#pragma unroll
        for (int j = 0; j < 16; j++) {
            ulonglong2 w = row[j];
            FMA2(acc[2 * j],     pe, w.x);
            FMA2(acc[2 * j + 1], pe, w.y);
        }
    }
    const int b = (int)(chain & 127u);
#pragma unroll
    for (int j = 0; j < 32; j++) {
        float a0, a1;
        unpack2(acc[j], a0, a1);
        int i0 = 2 * j, i1 = 2 * j + 1;
        a0 += g_dT[(k * 64 + i0) * 128 + b];
        a1 += g_dT[(k * 64 + i1) * 128 + b];
        g_epst[((size_t)(k * 64 + i0) << 17) + chain] = a0;
        g_epst[((size_t)(k * 64 + i1) << 17) + chain] = a1;
    }
}

// ---------------------------------------------------------------------------
// k_main: per-chain elementwise recursion + weights. q~ in registers.
// dyn smem: sU 8192 | sV 4096 | sPc 1024 | sLam 64  (53504 B)
// ---------------------------------------------------------------------------
__global__ void __launch_bounds__(256) k_main(const float* __restrict__ qn,
                                              Params prm) {
    extern __shared__ float dsm[];
    float* sU   = dsm;
    float* sV   = dsm + 8192;
    float* sPc  = dsm + 12288;
    float* sLam = dsm + 13312;
    const int t = threadIdx.x;
    const unsigned chain = (unsigned)blockIdx.x * 256u + (unsigned)t;
    const int b = (int)(chain & 127u);
    const int n = (int)(chain >> 7);

    for (int o = t; o < 8192; o += 256) sU[o] = g_uT[o];
    for (int o = t; o < 4096; o += 256) sV[o] = g_V[o];
    for (int o = t; o < 1024; o += 256) sPc[o] = g_pc[o];
    if (t < 64) sLam[t] = g_lam[t];
    __syncthreads();

    // q~0 = mu~ + (qn V)
    float qreg[64];
    const float4* qp = (const float4*)(qn + (size_t)chain * 64u);
#pragma unroll
    for (int j = 0; j < 16; j++) {
        float4 v = qp[j];
        qreg[4 * j] = v.x; qreg[4 * j + 1] = v.y;
        qreg[4 * j + 2] = v.z; qreg[4 * j + 3] = v.w;
    }
    unsigned long long acc[32];
#pragma unroll
    for (int j = 0; j < 32; j++) acc[j] = 0ull;
#pragma unroll 4
    for (int d = 0; d < 64; d++) {
        unsigned long long pe = pack2(qreg[d], qreg[d]);
        const ulonglong2* row = (const ulonglong2*)(sV + d * 64);
#pragma unroll
        for (int j = 0; j < 16; j++) {
            ulonglong2 w = row[j];
            FMA2(acc[2 * j],     pe, w.x);
            FMA2(acc[2 * j + 1], pe, w.y);
        }
    }
    float q[64];
#pragma unroll
    for (int j = 0; j < 32; j++) {
        float a0, a1;
        unpack2(acc[j], a0, a1);
        q[2 * j]     = a0 + g_mtT[(2 * j) * 128 + b];
        q[2 * j + 1] = a1 + g_mtT[(2 * j + 1) * 128 + b];
    }

    const float cw = g_cw[b];
    float slw;
    {
        float dot = 0.f, qsq = 0.f;
#pragma unroll
        for (int i = 0; i < 64; i++) {
            dot = fmaf(q[i], sU[i * 128 + b], dot);
            qsq = fmaf(sLam[i] * q[i], q[i], qsq);
        }
        float w = cw + dot - 0.5f * qsq;
        slw = (prm.beta[1] - prm.beta[0]) * w;
    }

    for (int k = 0; k < 16; k++) {
        const float* ep = g_epst + ((size_t)(k * 64) << 17) + chain;
#pragma unroll
        for (int i = 0; i < 64; i++) {
            float e = ep[(size_t)i << 17];
            q[i] = fmaf(sPc[k * 64 + i], q[i], e);
        }
        float dot = 0.f, qsq = 0.f;
#pragma unroll
        for (int i = 0; i < 64; i++) {
            dot = fmaf(q[i], sU[i * 128 + b], dot);
            qsq = fmaf(sLam[i] * q[i], q[i], qsq);
        }
        float w = cw + dot - 0.5f * qsq;
        slw = fmaf(prm.beta[k + 2] - prm.beta[k + 1], w, slw);
    }
    g_slw[b * 1024 + n] = slw;
}

// ---------------------------------------------------------------------------
// logsumexp over n, minus log(1024)
// ---------------------------------------------------------------------------
__global__ void k_reduce(float* __restrict__ out) {
    const int b = blockIdx.x;
    const int t = threadIdx.x;          // 128
    __shared__ float red[128];
    float m = -3.4e38f;
    for (int i = t; i < 1024; i += 128) m = fmaxf(m, g_slw[b * 1024 + i]);
    red[t] = m; __syncthreads();
    for (int s = 64; s > 0; s >>= 1) {
        if (t < s) red[t] = fmaxf(red[t], red[t + s]);
        __syncthreads();
    }
    float mx = red[0]; __syncthreads();
    float acc = 0.f;
    for (int i = t; i < 1024; i += 128) acc += expf(g_slw[b * 1024 + i] - mx);
    red[t] = acc; __syncthreads();
    for (int s = 64; s > 0; s >>= 1) {
        if (t < s) red[t] += red[t + s];
        __syncthreads();
    }
    if (t == 0) out[b] = mx + logf(red[0]) - 6.9314718055994531f;  // log(1024)
}

// ---------------------------------------------------------------------------
extern "C" void kernel_launch(void* const* d_in, const int* in_sizes, int n_in,
                              void* d_out, int out_size) {
    const float* x    = (const float*)d_in[0];
    const float* Wenc = (const float*)d_in[1];
    const float* Wdec = (const float*)d_in[2];
    const float* qn   = (const float*)d_in[3];
    // d_in[4] = p_noise — unused (momentum fully resampled each step)
    float* out = (float*)d_out;

    Params prm;
    double bb[18];
    for (int i = 0; i < 18; i++) {
        double z = 4.0 * (2.0 * ((double)i / 17.0) - 1.0);
        bb[i] = 1.0 / (1.0 + exp(-z));
    }
    for (int i = 0; i < 18; i++)
        prm.beta[i] = (float)((bb[i] - bb[0]) / (bb[17] - bb[0]));
    for (int k = 1; k <= 16; k++) {
        unsigned o0, o1;
        tf2x32(0u, 42u, 0u, (unsigned)k, &o0, &o1);   // fold_in(key(42), k)
        prm.fk0[k - 1] = o0; prm.fk1[k - 1] = o1;
    }

    cudaFuncSetAttribute(k_main, cudaFuncAttributeMaxDynamicSharedMemorySize, 53504);

    k_setup1<<<48, 256>>>(x, Wenc, Wdec);
    k_cw<<<1, 128>>>(x);
    k_jacobi<<<1, 1024>>>();
    k_trans<<<32, 256>>>();
    k_coef<<<16, 256>>>(prm);
    k_eps<<<8192, 256>>>(prm);
    k_main<<<512, 256, 53504>>>(qn, prm);
    k_reduce<<<128, 128>>>(out);
}

// round 8
// speedup vs baseline: 2.7671x; 1.0669x over previous
#include <cuda_runtime.h>
#include <math.h>

struct Params {
    float beta[18];
    unsigned fk0[16];
    unsigned fk1[16];
};

// -------- device scratch (allocation-free, module statics) --------
__device__ float g_M[4096];          // W_dec W_dec^T
__device__ float g_mu[8192];         // [b][d]
__device__ float g_xWt[8192];        // [b][d] x W_dec^T
__device__ float g_V[4096];          // eigenvectors [d][i]
__device__ float g_lam[64];          // eigenvalues
__device__ float g_mtT[8192];        // [i][b]  mu~  (mu V)
__device__ float g_xtT[8192];        // [i][b]  xWt~ (xWt V)
__device__ float g_uT[8192];         // [i][b]  u~ = xWt~ - mu~
__device__ float g_cw[128];          // const_b
__device__ float g_pc[1024];         // [k][i] p coefficient
__device__ float g_qd[1024];         // [k][i] noise coefficient (x sqrt2 folded)
__device__ float g_dT[16 * 8192];    // [k][i][b] drift
__device__ float g_epst[134217728];  // [k][i][chain] qd*eps~ + d~  (512MB)
__device__ float g_slw[131072];      // [b][n]

// ---------------------------------------------------------------------------
// threefry2x32 — exact JAX schedule
// ---------------------------------------------------------------------------
__host__ __device__ __forceinline__ void tf2x32(unsigned k0, unsigned k1,
                                                unsigned x0, unsigned x1,
                                                unsigned* o0, unsigned* o1) {
    unsigned k2 = k0 ^ k1 ^ 0x1BD11BDAu;
    x0 += k0; x1 += k1;
#define TFR(r) { x0 += x1; x1 = (x1 << (r)) | (x1 >> (32 - (r))); x1 ^= x0; }
    TFR(13) TFR(15) TFR(26) TFR(6)
    x0 += k1; x1 += k2 + 1u;
    TFR(17) TFR(29) TFR(16) TFR(24)
    x0 += k2; x1 += k0 + 2u;
    TFR(13) TFR(15) TFR(26) TFR(6)
    x0 += k0; x1 += k1 + 3u;
    TFR(17) TFR(29) TFR(16) TFR(24)
    x0 += k1; x1 += k2 + 4u;
    TFR(13) TFR(15) TFR(26) TFR(6)
    x0 += k2; x1 += k0 + 5u;
#undef TFR
    *o0 = x0; *o1 = x1;
}

// partitionable-mode draw: bits = out0 ^ out1 of cipher(key, (0, idx)).
// Returns erfinv(u); the sqrt(2) factor is folded into g_qd.
__device__ __forceinline__ float draw_erfinv(unsigned fk0, unsigned fk1, unsigned idx) {
    unsigned r0, r1;
    tf2x32(fk0, fk1, 0u, idx, &r0, &r1);
    unsigned bits = r0 ^ r1;
    float f = __uint_as_float((bits >> 9) | 0x3f800000u) - 1.0f;  // [0,1)
    const float lo = -0.99999994f;                  // nextafterf(-1,0)
    float v = fmaf(f, 2.0f, lo);                    // (hi-lo) == 2.0f in fp32
    v = fmaxf(lo, v);
    return erfinvf(v);
}

// -------- packed f32x2 helpers --------
__device__ __forceinline__ unsigned long long pack2(float a, float b) {
    unsigned long long r;
    asm("mov.b64 %0, {%1, %2};" : "=l"(r) : "f"(a), "f"(b));
    return r;
}
__device__ __forceinline__ void unpack2(unsigned long long v, float& a, float& b) {
    asm("mov.b64 {%0, %1}, %2;" : "=f"(a), "=f"(b) : "l"(v));
}
#define FMA2(c, a, bb) asm("fma.rn.f32x2 %0, %1, %2, %0;" : "+l"(c) : "l"(a), "l"(bb))

// ---------------------------------------------------------------------------
// setup: M, mu, xWt
// ---------------------------------------------------------------------------
__global__ void k_setup1(const float* __restrict__ x,
                         const float* __restrict__ We,
                         const float* __restrict__ Wd) {
    int idx = blockIdx.x * 256 + threadIdx.x;
    if (idx < 4096) {
        int i = idx >> 6, j = idx & 63;
        float s = 0.f;
        for (int e = 0; e < 64; e++) s = fmaf(Wd[i * 64 + e], Wd[j * 64 + e], s);
        g_M[idx] = s;
    } else if (idx < 12288) {
        int o = idx - 4096; int b = o >> 6, d = o & 63;
        float sm = 0.f, sw = 0.f;
        for (int e = 0; e < 64; e++) {
            float xe = x[b * 64 + e];
            sm = fmaf(xe, We[e * 64 + d], sm);
            sw = fmaf(xe, Wd[d * 64 + e], sw);
        }
        g_mu[o] = sm; g_xWt[o] = sw;
    }
}

// const_b = 0.5||mu||^2 - 0.5||x||^2 - 32 log 2pi
__global__ void k_cw(const float* __restrict__ x) {
    int b = threadIdx.x;
    float s = 0.f, sx = 0.f;
    for (int d = 0; d < 64; d++) {
        float m = g_mu[b * 64 + d]; s = fmaf(m, m, s);
        float xe = x[b * 64 + d];   sx = fmaf(xe, xe, sx);
    }
    g_cw[b] = 0.5f * s - 0.5f * sx - 58.81206612509905f;
}

// ---------------------------------------------------------------------------
// parallel two-sided Jacobi eigensolver, 64x64, one block of 1024 threads.
// ---------------------------------------------------------------------------
__global__ void __launch_bounds__(1024) k_jacobi() {
    __shared__ float A[64][65];
    __shared__ float Vv[64][65];
    __shared__ float cs[32], sn[32];
    __shared__ int pp[32], qq[32];
    const int t = threadIdx.x;
    for (int o = t; o < 4096; o += 1024) {
        int i = o >> 6, j = o & 63;
        A[i][j] = g_M[o];
        Vv[i][j] = (i == j) ? 1.f : 0.f;
    }
    __syncthreads();
    for (int sweep = 0; sweep < 7; sweep++) {
        for (int r = 0; r < 63; r++) {
            if (t < 32) {
                int p, q;
                if (t == 0) { p = 63; q = r; }
                else { p = (r + t) % 63; q = (r - t + 63) % 63; }
                if (p > q) { int tmp = p; p = q; q = tmp; }
                pp[t] = p; qq[t] = q;
                float apq = A[p][q], app = A[p][p], aqq = A[q][q];
                float c = 1.f, s = 0.f;
                if (fabsf(apq) > 1e-30f) {
                    float tau = (aqq - app) / (2.f * apq);
                    float tt = ((tau >= 0.f) ? 1.f : -1.f) /
                               (fabsf(tau) + sqrtf(1.f + tau * tau));
                    c = rsqrtf(1.f + tt * tt);
                    s = tt * c;
                }
                cs[t] = c; sn[t] = s;
            }
            __syncthreads();
            for (int u = t; u < 2048; u += 1024) {
                int m = u >> 6, j = u & 63;
                int p = pp[m], q = qq[m];
                float c = cs[m], s = sn[m];
                float ap = A[p][j], aq = A[q][j];
                A[p][j] = c * ap - s * aq;
                A[q][j] = s * ap + c * aq;
            }
            __syncthreads();
            for (int u = t; u < 2048; u += 1024) {
                int m = u >> 6, i = u & 63;
                int p = pp[m], q = qq[m];
                float c = cs[m], s = sn[m];
                float ap = A[i][p], aq = A[i][q];
                A[i][p] = c * ap - s * aq;
                A[i][q] = s * ap + c * aq;
                float vp = Vv[i][p], vq = Vv[i][q];
                Vv[i][p] = c * vp - s * vq;
                Vv[i][q] = s * vp + c * vq;
            }
            __syncthreads();
        }
    }
    for (int o = t; o < 4096; o += 1024) g_V[o] = Vv[o >> 6][o & 63];
    if (t < 64) g_lam[t] = A[t][t];
}

// ---------------------------------------------------------------------------
// transform mu, xWt into eigenbasis: [i][b] tables
// ---------------------------------------------------------------------------
__global__ void k_trans() {
    int o = blockIdx.x * 256 + threadIdx.x;   // 8192
    int b = o >> 6, i = o & 63;
    float sm = 0.f, sx = 0.f;
    for (int d = 0; d < 64; d++) {
        float v = g_V[d * 64 + i];
        sm = fmaf(g_mu[b * 64 + d], v, sm);
        sx = fmaf(g_xWt[b * 64 + d], v, sx);
    }
    g_mtT[i * 128 + b] = sm;
    g_xtT[i * 128 + b] = sx;
    g_uT[i * 128 + b] = sx - sm;
}

// ---------------------------------------------------------------------------
// per-step scalar coefficients + drift (diagonal in eigenbasis)
// c = h^2(bk*lam+1); p = 1-4.5c+3c^2-0.5c^3; qd = sqrt2*h(3-4c+c^2);
// d~ = h^2(4.5-3c+0.5c^2) * (bk*xWt~ + (1-bk)*mu~)
// ---------------------------------------------------------------------------
__global__ void k_coef(Params prm) {
    const int k = blockIdx.x;
    const float bk = prm.beta[k + 1];
    const float h = 0.05f, h2 = 0.0025f;
    for (int o = threadIdx.x; o < 8192; o += 256) {
        int i = o >> 7, b = o & 127;
        float lam = g_lam[i];
        float c = h2 * (bk * lam + 1.f);
        float sd = h2 * (4.5f - 3.f * c + 0.5f * c * c);
        float vt = bk * g_xtT[i * 128 + b] + (1.f - bk) * g_mtT[i * 128 + b];
        g_dT[(k * 64 + i) * 128 + b] = sd * vt;
        if (b == 0) {
            g_pc[k * 64 + i] = 1.f - 4.5f * c + 3.f * c * c - 0.5f * c * c * c;
            g_qd[k * 64 + i] = 1.41421356237f * h * (3.f - 4.f * c + c * c);
        }
    }
}

// ---------------------------------------------------------------------------
// k_eps: stateless over (chain, step). Draw 64 erfinv values, multiply by
// sVq = V * qd(k) (sqrt2 folded), add drift, store g_epst[k][i][chain].
// 128 threads: b == threadIdx.x exactly (chain 128-aligned per block).
// ---------------------------------------------------------------------------
__global__ void __launch_bounds__(128) k_eps(Params prm) {
    __shared__ float sVq[4096];               // [d][i] = V[d][i] * qd[k][i]
    const int k  = blockIdx.x >> 10;
    const int cb = blockIdx.x & 1023;
    const int t  = threadIdx.x;
    const unsigned chain = (unsigned)cb * 128u + (unsigned)t;
    for (int o = t; o < 4096; o += 128)
        sVq[o] = g_V[o] * g_qd[k * 64 + (o & 63)];
    __syncthreads();

    const unsigned fk0 = prm.fk0[k], fk1 = prm.fk1[k];
    const unsigned base = chain * 64u;
    unsigned long long acc[32];
#pragma unroll
    for (int j = 0; j < 32; j++) acc[j] = 0ull;

#pragma unroll 2
    for (int d = 0; d < 64; d++) {
        float e = draw_erfinv(fk0, fk1, base + (unsigned)d);
        unsigned long long pe = pack2(e, e);
        const ulonglong2* row = (const ulonglong2*)(sVq + d * 64);
#pragma unroll
        for (int j = 0; j < 16; j++) {
            ulonglong2 w = row[j];
            FMA2(acc[2 * j],     pe, w.x);
            FMA2(acc[2 * j + 1], pe, w.y);
        }
    }
#pragma unroll
    for (int j = 0; j < 32; j++) {
        float a0, a1;
        unpack2(acc[j], a0, a1);
        int i0 = 2 * j, i1 = 2 * j + 1;
        a0 += g_dT[(k * 64 + i0) * 128 + t];
        a1 += g_dT[(k * 64 + i1) * 128 + t];
        g_epst[((size_t)(k * 64 + i0) << 17) + chain] = a0;
        g_epst[((size_t)(k * 64 + i1) << 17) + chain] = a1;
    }
}

// ---------------------------------------------------------------------------
// k_main: per-chain elementwise recursion + weights. q~ in registers.
// 128 threads/block: b == t, n == blockIdx.x.
// dyn smem: sU 8192 | sV 4096 | sPc 1024 | sLam 64  (53504 B)
// ---------------------------------------------------------------------------
__global__ void __launch_bounds__(128) k_main(const float* __restrict__ qn,
                                              Params prm) {
    extern __shared__ float dsm[];
    float* sU   = dsm;
    float* sV   = dsm + 8192;
    float* sPc  = dsm + 12288;
    float* sLam = dsm + 13312;
    const int t = threadIdx.x;
    const unsigned chain = (unsigned)blockIdx.x * 128u + (unsigned)t;
    const int b = t;
    const int n = blockIdx.x;

    for (int o = t; o < 8192; o += 128) sU[o] = g_uT[o];
    for (int o = t; o < 4096; o += 128) sV[o] = g_V[o];
    for (int o = t; o < 1024; o += 128) sPc[o] = g_pc[o];
    if (t < 64) sLam[t] = g_lam[t];
    __syncthreads();

    // q~0 = mu~ + (qn V)
    float qreg[64];
    const float4* qp = (const float4*)(qn + (size_t)chain * 64u);
#pragma unroll
    for (int j = 0; j < 16; j++) {
        float4 v = qp[j];
        qreg[4 * j] = v.x; qreg[4 * j + 1] = v.y;
        qreg[4 * j + 2] = v.z; qreg[4 * j + 3] = v.w;
    }
    unsigned long long acc[32];
#pragma unroll
    for (int j = 0; j < 32; j++) acc[j] = 0ull;
#pragma unroll 4
    for (int d = 0; d < 64; d++) {
        unsigned long long pe = pack2(qreg[d], qreg[d]);
        const ulonglong2* row = (const ulonglong2*)(sV + d * 64);
#pragma unroll
        for (int j = 0; j < 16; j++) {
            ulonglong2 w = row[j];
            FMA2(acc[2 * j],     pe, w.x);
            FMA2(acc[2 * j + 1], pe, w.y);
        }
    }
    float q[64];
#pragma unroll
    for (int j = 0; j < 32; j++) {
        float a0, a1;
        unpack2(acc[j], a0, a1);
        q[2 * j]     = a0 + g_mtT[(2 * j) * 128 + b];
        q[2 * j + 1] = a1 + g_mtT[(2 * j + 1) * 128 + b];
    }

    const float cw = g_cw[b];
    float slw;
    {
        float dot = 0.f, qsq = 0.f;
#pragma unroll
        for (int i = 0; i < 64; i++) {
            dot = fmaf(q[i], sU[i * 128 + b], dot);
            qsq = fmaf(sLam[i] * q[i], q[i], qsq);
        }
        float w = cw + dot - 0.5f * qsq;
        slw = (prm.beta[1] - prm.beta[0]) * w;
    }

    for (int k = 0; k < 16; k++) {
        const float* ep = g_epst + ((size_t)(k * 64) << 17) + chain;
#pragma unroll
        for (int i = 0; i < 64; i++) {
            float e = __ldg(ep + ((size_t)i << 17));
            q[i] = fmaf(sPc[k * 64 + i], q[i], e);
        }
        float dot = 0.f, qsq = 0.f;
#pragma unroll
        for (int i = 0; i < 64; i++) {
            dot = fmaf(q[i], sU[i * 128 + b], dot);
            qsq = fmaf(sLam[i] * q[i], q[i], qsq);
        }
        float w = cw + dot - 0.5f * qsq;
        slw = fmaf(prm.beta[k + 2] - prm.beta[k + 1], w, slw);
    }
    g_slw[b * 1024 + n] = slw;
}

// ---------------------------------------------------------------------------
// logsumexp over n, minus log(1024)
// ---------------------------------------------------------------------------
__global__ void k_reduce(float* __restrict__ out) {
    const int b = blockIdx.x;
    const int t = threadIdx.x;          // 128
    __shared__ float red[128];
    float m = -3.4e38f;
    for (int i = t; i < 1024; i += 128) m = fmaxf(m, g_slw[b * 1024 + i]);
    red[t] = m; __syncthreads();
    for (int s = 64; s > 0; s >>= 1) {
        if (t < s) red[t] = fmaxf(red[t], red[t + s]);
        __syncthreads();
    }
    float mx = red[0]; __syncthreads();
    float acc = 0.f;
    for (int i = t; i < 1024; i += 128) acc += expf(g_slw[b * 1024 + i] - mx);
    red[t] = acc; __syncthreads();
    for (int s = 64; s > 0; s >>= 1) {
        if (t < s) red[t] += red[t + s];
        __syncthreads();
    }
    if (t == 0) out[b] = mx + logf(red[0]) - 6.9314718055994531f;  // log(1024)
}

// ---------------------------------------------------------------------------
extern "C" void kernel_launch(void* const* d_in, const int* in_sizes, int n_in,
                              void* d_out, int out_size) {
    const float* x    = (const float*)d_in[0];
    const float* Wenc = (const float*)d_in[1];
    const float* Wdec = (const float*)d_in[2];
    const float* qn   = (const float*)d_in[3];
    // d_in[4] = p_noise — unused (momentum fully resampled each step)
    float* out = (float*)d_out;

    Params prm;
    double bb[18];
    for (int i = 0; i < 18; i++) {
        double z = 4.0 * (2.0 * ((double)i / 17.0) - 1.0);
        bb[i] = 1.0 / (1.0 + exp(-z));
    }
    for (int i = 0; i < 18; i++)
        prm.beta[i] = (float)((bb[i] - bb[0]) / (bb[17] - bb[0]));
    for (int k = 1; k <= 16; k++) {
        unsigned o0, o1;
        tf2x32(0u, 42u, 0u, (unsigned)k, &o0, &o1);   // fold_in(key(42), k)
        prm.fk0[k - 1] = o0; prm.fk1[k - 1] = o1;
    }

    cudaFuncSetAttribute(k_main, cudaFuncAttributeMaxDynamicSharedMemorySize, 53504);

    k_setup1<<<48, 256>>>(x, Wenc, Wdec);
    k_cw<<<1, 128>>>(x);
    k_jacobi<<<1, 1024>>>();
    k_trans<<<32, 256>>>();
    k_coef<<<16, 256>>>(prm);
    k_eps<<<16384, 128>>>(prm);
    k_main<<<1024, 128, 53504>>>(qn, prm);
    k_reduce<<<128, 128>>>(out);
}